// round 11
// baseline (speedup 1.0000x reference)
#include <cuda_runtime.h>
#include <math.h>
#include <cstdint>

#define Bn 8
#define Tn 2048
#define Cn 1024
#define Hn 256
#define Mn (Bn * Tn)   // 16384

// Scratch (allocation-free rule: __device__ globals)
__device__ float g_Q[Mn * Hn];       // [b][T][H]  (tf32-rounded)
__device__ float g_K[Mn * Hn];       // [b][T][H]  (tf32-rounded)
__device__ float g_V[Mn * Hn];       // [b][T][H]  (tf32-rounded)
__device__ float g_Qp[Mn * Hn];      // Q packed as mma A-fragments (scaled)
__device__ float g_Kp[Mn * Hn];      // K packed as S-GEMM B-fragments (float2, wn4)
__device__ float g_Vp[Mn * Hn];      // V packed as PV B-fragments (wn4)
__device__ float g_Wp[3 * Hn * Cn];  // W packed as proj B-fragments (tf32 RNA)

// ---------------------------------------------------------------------------
// Helpers
// ---------------------------------------------------------------------------
__device__ __forceinline__ uint32_t smem_u32(const void* p) {
    uint32_t a;
    asm("{ .reg .u64 t; cvta.to.shared.u64 t, %1; cvt.u32.u64 %0, t; }"
        : "=r"(a) : "l"(p));
    return a;
}
__device__ __forceinline__ uint32_t f2tf32(float f) {
    uint32_t u;
    asm("cvt.rna.tf32.f32 %0, %1;" : "=r"(u) : "f"(f));
    return u;
}
__device__ __forceinline__ void cp_async16(uint32_t saddr, const void* g) {
    asm volatile("cp.async.cg.shared.global [%0], [%1], 16;"
                 :: "r"(saddr), "l"(g) : "memory");
}
__device__ __forceinline__ void cp_commit() {
    asm volatile("cp.async.commit_group;" ::: "memory");
}
__device__ __forceinline__ void mma_tf32(float* c, const uint32_t* a, const uint32_t* b) {
    asm volatile(
        "mma.sync.aligned.m16n8k8.row.col.f32.tf32.tf32.f32 "
        "{%0,%1,%2,%3}, {%4,%5,%6,%7}, {%8,%9}, {%0,%1,%2,%3};"
        : "+f"(c[0]), "+f"(c[1]), "+f"(c[2]), "+f"(c[3])
        : "r"(a[0]), "r"(a[1]), "r"(a[2]), "r"(a[3]), "r"(b[0]), "r"(b[1]));
}

// ---------------------------------------------------------------------------
// Pack W into proj B-fragment order, tf32-rounded (RNA). (unchanged R10)
// ---------------------------------------------------------------------------
__global__ __launch_bounds__(256)
void pack_w_kernel(const float* __restrict__ Wq,
                   const float* __restrict__ Wk,
                   const float* __restrict__ Wv) {
    __shared__ float vs[32][260];
    const int t     = blockIdx.x;
    const int which = blockIdx.y;
    const int tid   = threadIdx.x;
    const float* W = (which == 0) ? Wq : (which == 1 ? Wk : Wv);

    #pragma unroll
    for (int it = 0; it < 8; it++) {
        int f = tid + it * 256;
        int r = f >> 6, c4 = (f & 63) * 4;
        *(float4*)&vs[r][c4] = *(const float4*)&W[(size_t)(t * 32 + r) * Hn + c4];
    }
    __syncthreads();

    float* dstw = g_Wp + (size_t)which * 2 * 32 * 4096;
    #pragma unroll
    for (int it = 0; it < 8; it++) {
        int f = tid + it * 256;
        int n0b = f >> 10, rem = f & 1023;
        int k8 = rem >> 8, wn = (rem >> 7) & 1, ntp = (rem >> 5) & 3, lane = rem & 31;
        int g = lane >> 2, tt = lane & 3;
        int kc = k8 * 8 + tt;
        int n_a = n0b * 128 + wn * 64 + ntp * 16 + g, n_b = n_a + 8;
        float* dst = dstw + ((size_t)n0b * 32 + t) * 4096 + (size_t)rem * 4;
        *(float4*)dst = make_float4(
            __uint_as_float(f2tf32(vs[kc][n_a])),
            __uint_as_float(f2tf32(vs[kc + 4][n_a])),
            __uint_as_float(f2tf32(vs[kc][n_b])),
            __uint_as_float(f2tf32(vs[kc + 4][n_b])));
    }
}

// ---------------------------------------------------------------------------
// Projection via mma.sync tf32, B pre-packed. (unchanged R10)
// ---------------------------------------------------------------------------
#define AROW 36
#define ATILE_B (128 * AROW * 4)
#define BTILE_B 16384
#define OFF_PA0 0
#define OFF_PA1 ATILE_B
#define OFF_PB0 (2 * ATILE_B)
#define OFF_PB1 (2 * ATILE_B + BTILE_B)
#define PROJ_SMEM (2 * ATILE_B + 2 * BTILE_B)

__global__ __launch_bounds__(256, 2)
void proj_wmma_kernel(const float* __restrict__ x) {
    extern __shared__ char smem[];
    const uint32_t sb = smem_u32(smem);

    const int tid  = threadIdx.x;
    const int warp = tid >> 5, lane = tid & 31;
    const int group = lane >> 2, tig = lane & 3;
    const int wm = warp & 3, wn = warp >> 2;
    const int which = blockIdx.z;
    const int m0 = blockIdx.x * 128;
    const int n0b = blockIdx.y;

    const float* A = x + (size_t)m0 * Cn;
    const float* Bp = g_Wp + (((size_t)which * 2 + n0b) * 32) * 4096;
    float* outp = ((which == 0) ? g_Q : (which == 1 ? g_K : g_V))
                  + (size_t)m0 * Hn + n0b * 128;

    const int r0f = tid >> 3;
    const int ccf = (tid & 7) * 4;

    auto fill = [&](int t, int bsel) {
        const uint32_t aOff = sb + (bsel ? OFF_PA1 : OFF_PA0);
        const uint32_t bOff = sb + (bsel ? OFF_PB1 : OFF_PB0);
        #pragma unroll
        for (int it = 0; it < 4; it++) {
            int row = r0f + 32 * it;
            cp_async16(aOff + (uint32_t)(row * AROW + ccf) * 4,
                       A + (size_t)row * Cn + t * 32 + ccf);
        }
        const float* Bt = Bp + (size_t)t * 4096;
        #pragma unroll
        for (int it = 0; it < 4; it++) {
            int f = tid + it * 256;
            cp_async16(bOff + (uint32_t)f * 16, Bt + (size_t)f * 4);
        }
    };

    float acc[2][8][4];
    #pragma unroll
    for (int mt = 0; mt < 2; mt++)
        #pragma unroll
        for (int nt = 0; nt < 8; nt++)
            #pragma unroll
            for (int q = 0; q < 4; q++) acc[mt][nt][q] = 0.f;

    fill(0, 0);
    cp_commit();

    const int NT = Cn / 32;
    #pragma unroll 1
    for (int t = 0; t < NT; t++) {
        if (t + 1 < NT) {
            fill(t + 1, (t + 1) & 1);
            cp_commit();
            asm volatile("cp.async.wait_group 1;" ::: "memory");
        } else {
            asm volatile("cp.async.wait_group 0;" ::: "memory");
        }
        __syncthreads();

        const float* As = (const float*)(smem + ((t & 1) ? OFF_PA1 : OFF_PA0));
        const float4* Bs4 = (const float4*)(smem + ((t & 1) ? OFF_PB1 : OFF_PB0));

        #pragma unroll
        for (int k8 = 0; k8 < 4; k8++) {
            uint32_t a[2][4];
            #pragma unroll
            for (int mt = 0; mt < 2; mt++) {
                int m = wm * 32 + mt * 16 + group;
                a[mt][0] = f2tf32(As[m * AROW + k8 * 8 + tig]);
                a[mt][1] = f2tf32(As[(m + 8) * AROW + k8 * 8 + tig]);
                a[mt][2] = f2tf32(As[m * AROW + k8 * 8 + tig + 4]);
                a[mt][3] = f2tf32(As[(m + 8) * AROW + k8 * 8 + tig + 4]);
            }
            #pragma unroll
            for (int ntp = 0; ntp < 4; ntp++) {
                float4 bv = Bs4[((k8 * 2 + wn) * 4 + ntp) * 32 + lane];
                uint32_t b0[2] = {__float_as_uint(bv.x), __float_as_uint(bv.y)};
                uint32_t b1[2] = {__float_as_uint(bv.z), __float_as_uint(bv.w)};
                #pragma unroll
                for (int mt = 0; mt < 2; mt++) {
                    mma_tf32(acc[mt][2 * ntp],     a[mt], b0);
                    mma_tf32(acc[mt][2 * ntp + 1], a[mt], b1);
                }
            }
        }
        __syncthreads();
    }

    #pragma unroll
    for (int mt = 0; mt < 2; mt++) {
        int m = wm * 32 + mt * 16 + group;
        #pragma unroll
        for (int nt = 0; nt < 8; nt++) {
            int col = wn * 64 + nt * 8 + 2 * tig;
            *(float2*)&outp[(size_t)m * Hn + col] =
                make_float2(__uint_as_float(f2tf32(acc[mt][nt][0])),
                            __uint_as_float(f2tf32(acc[mt][nt][1])));
            *(float2*)&outp[(size_t)(m + 8) * Hn + col] =
                make_float2(__uint_as_float(f2tf32(acc[mt][nt][2])),
                            __uint_as_float(f2tf32(acc[mt][nt][3])));
        }
    }
}

// ---------------------------------------------------------------------------
// Pack Q into A-fragment order (scaled by 1/16), per 16-row block. (unchanged)
// ---------------------------------------------------------------------------
__global__ __launch_bounds__(256)
void pack_q_kernel() {
    __shared__ float vs[32][260];
    const int b   = blockIdx.y;
    const int t0  = blockIdx.x * 32;
    const int tid = threadIdx.x;
    const float* src = g_Q + ((size_t)b * Tn + t0) * Hn;
    float* dst = g_Qp + ((size_t)b * (Tn / 16) + blockIdx.x * 2) * 4096;
    const float scale = 0.0625f;

    #pragma unroll
    for (int it = 0; it < 8; it++) {
        int f = tid + it * 256;
        int r = f >> 6, c4 = (f & 63) * 4;
        float4 v = *(const float4*)&src[(size_t)r * Hn + c4];
        v.x *= scale; v.y *= scale; v.z *= scale; v.w *= scale;
        *(float4*)&vs[r][c4] = v;
    }
    __syncthreads();

    #pragma unroll
    for (int it = 0; it < 8; it++) {
        int f = tid + it * 256;
        int blk = f >> 10, rem = f & 1023;
        int k8 = rem >> 5, lane = rem & 31;
        int g = lane >> 2, t = lane & 3;
        int r0 = blk * 16 + g, r1 = r0 + 8;
        int c = k8 * 8 + t;
        *(float4*)&dst[(size_t)f * 4] =
            make_float4(vs[r0][c], vs[r1][c], vs[r0][c + 4], vs[r1][c + 4]);
    }
}

// ---------------------------------------------------------------------------
// Pack K: per 32-key block, [k8(32)][wn4(4)][lane(32)] float2 =
//   {K[n][c], K[n][c+4]},  n = wn4*8 + g,  c = k8*8 + t
// ---------------------------------------------------------------------------
__global__ __launch_bounds__(256)
void pack_k_kernel() {
    __shared__ float vs[32][260];
    const int b   = blockIdx.y;
    const int t0  = blockIdx.x * 32;
    const int tid = threadIdx.x;
    const float* src = g_K + ((size_t)b * Tn + t0) * Hn;
    float* dst = g_Kp + ((size_t)b * (Tn / 32) + blockIdx.x) * 8192;

    #pragma unroll
    for (int it = 0; it < 8; it++) {
        int f = tid + it * 256;
        int r = f >> 6, c4 = (f & 63) * 4;
        *(float4*)&vs[r][c4] = *(const float4*)&src[(size_t)r * Hn + c4];
    }
    __syncthreads();

    // 4096 float2 entries, 16 per thread
    #pragma unroll
    for (int it = 0; it < 16; it++) {
        int f2 = tid + it * 256;
        int k8 = f2 >> 7, wn4 = (f2 >> 5) & 3, lane = f2 & 31;
        int g = lane >> 2, t = lane & 3;
        int n = wn4 * 8 + g;
        int c = k8 * 8 + t;
        *(float2*)&dst[(size_t)f2 * 2] = make_float2(vs[n][c], vs[n][c + 4]);
    }
}

// ---------------------------------------------------------------------------
// Pack V: per 32-key block, [k8i(4)][wn4(4)][ntp(4)][lane(32)][4] =
//   {V[k0][d0], V[k1][d0], V[k0][d1], V[k1][d1]},
//   k0=k8i*8+tig, k1=k0+4, d0=wn4*64+2*ntp*8+g, d1=d0+8
// ---------------------------------------------------------------------------
__global__ __launch_bounds__(256)
void pack_v_kernel() {
    __shared__ float vs[32][260];
    const int b   = blockIdx.y;
    const int t0  = blockIdx.x * 32;
    const int tid = threadIdx.x;
    const float* src = g_V + ((size_t)b * Tn + t0) * Hn;
    float* dst = g_Vp + ((size_t)b * (Tn / 32) + blockIdx.x) * 8192;

    #pragma unroll
    for (int it = 0; it < 8; it++) {
        int f = tid + it * 256;
        int r = f >> 6, c4 = (f & 63) * 4;
        *(float4*)&vs[r][c4] = *(const float4*)&src[(size_t)r * Hn + c4];
    }
    __syncthreads();

    #pragma unroll
    for (int it = 0; it < 8; it++) {
        int f = tid + it * 256;
        int k8i = f >> 9, wn4 = (f >> 7) & 3, ntp = (f >> 5) & 3, lane = f & 31;
        int group = lane >> 2, tig = lane & 3;
        int k0 = k8i * 8 + tig, k1 = k0 + 4;
        int d0 = wn4 * 64 + 2 * ntp * 8 + group, d1 = d0 + 8;
        *(float4*)&dst[(size_t)f * 4] =
            make_float4(vs[k0][d0], vs[k1][d0], vs[k0][d1], vs[k1][d1]);
    }
}

// ---------------------------------------------------------------------------
// Causal flash attention, mma.sync tf32, 512 threads (16 warps, 4/SMSP).
// BM=64, BN=32. wm=warp>>2 (16-row group), wn=warp&3 (8-key / 64-dim slice).
// Per warp: S = 16x8 (even/odd-k8 split accumulators), PV = 16x64 (o[8][4]).
// ---------------------------------------------------------------------------
#define QP_BYTES 65536
#define KBUF 32768
#define OFF_QP 0
#define OFF_K0 QP_BYTES
#define OFF_V0 (OFF_K0 + 2 * KBUF)
#define OFF_PS (OFF_V0 + 2 * KBUF)          // 196608
#define PADP 36
#define OFF_RED (OFF_PS + 64 * PADP * 4)    // 205824
#define ATTN_SMEM (OFF_RED + 2048)          // 207872

__global__ __launch_bounds__(512, 1)
void attn_mma_kernel(float* __restrict__ out) {
    extern __shared__ char smem[];
    const uint32_t sb = smem_u32(smem);
    float* Ps = (float*)(smem + OFF_PS);      // [64][36]
    float* redmax = (float*)(smem + OFF_RED); // [4][64]
    float* redsum = redmax + 256;             // [4][64]

    const int b   = blockIdx.y;
    const int m0  = ((int)gridDim.x - 1 - (int)blockIdx.x) * 64;
    const int tid = threadIdx.x;
    const int warp = tid >> 5, lane = tid & 31;
    const int group = lane >> 2, tig = lane & 3;
    const int wm = warp >> 2, wn = warp & 3;

    const float* Qpb = g_Qp + ((size_t)b * (Tn / 16) + m0 / 16) * 4096;
    const float* Kpb = g_Kp + (size_t)b * (Tn / 32) * 8192;
    const float* Vpb = g_Vp + (size_t)b * (Tn / 32) * 8192;

    auto fillK = [&](int t, int bs) {
        const uint32_t off = sb + OFF_K0 + bs * KBUF;
        const float* src = Kpb + (size_t)t * 8192;
        #pragma unroll
        for (int it = 0; it < 4; it++) {
            int f = tid + it * 512;
            cp_async16(off + (uint32_t)f * 16, src + (size_t)f * 4);
        }
    };
    auto fillV = [&](int t, int bs) {
        const uint32_t off = sb + OFF_V0 + bs * KBUF;
        const float* src = Vpb + (size_t)t * 8192;
        #pragma unroll
        for (int it = 0; it < 4; it++) {
            int f = tid + it * 512;
            cp_async16(off + (uint32_t)f * 16, src + (size_t)f * 4);
        }
    };

    // Stage Q (4096 float4) + first K/V
    #pragma unroll
    for (int it = 0; it < 8; it++) {
        int f = tid + it * 512;
        cp_async16(sb + OFF_QP + (uint32_t)f * 16, Qpb + (size_t)f * 4);
    }
    fillK(0, 0);
    fillV(0, 0);
    cp_commit();

    const int r0 = wm * 16 + group;           // owned rows r0, r0+8
    float m_run0 = -INFINITY, m_run1 = -INFINITY;
    float l_run0 = 0.f, l_run1 = 0.f;
    float o[8][4];
    #pragma unroll
    for (int nt = 0; nt < 8; nt++)
        #pragma unroll
        for (int q = 0; q < 4; q++) o[nt][q] = 0.f;

    const int NT = m0 / 32 + 2;
    #pragma unroll 1
    for (int t = 0; t < NT; t++) {
        const int bs = t & 1;
        if (t + 1 < NT) {
            fillK(t + 1, bs ^ 1);
            fillV(t + 1, bs ^ 1);
            cp_commit();
            asm volatile("cp.async.wait_group 1;" ::: "memory");
        } else {
            asm volatile("cp.async.wait_group 0;" ::: "memory");
        }
        __syncthreads();

        const float4* Qw  = (const float4*)(smem + OFF_QP) + wm * 1024;
        const float2* Ks2 = (const float2*)(smem + OFF_K0 + bs * KBUF);
        const float4* Vp4 = (const float4*)(smem + OFF_V0 + bs * KBUF);
        const int kv0 = t * 32;

        // ---- S = Q K^T: 1 n-tile, even/odd k8 split accumulators ----
        float se[4] = {0.f, 0.f, 0.f, 0.f};
        float so[4] = {0.f, 0.f, 0.f, 0.f};
        #pragma unroll 4
        for (int k8 = 0; k8 < 32; k8 += 2) {
            float4 qa = Qw[k8 * 32 + lane];
            float2 kb = Ks2[(k8 * 4 + wn) * 32 + lane];
            uint32_t a[4] = {__float_as_uint(qa.x), __float_as_uint(qa.y),
                             __float_as_uint(qa.z), __float_as_uint(qa.w)};
            uint32_t bb[2] = {__float_as_uint(kb.x), __float_as_uint(kb.y)};
            mma_tf32(se, a, bb);

            float4 qa2 = Qw[(k8 + 1) * 32 + lane];
            float2 kb2 = Ks2[((k8 + 1) * 4 + wn) * 32 + lane];
            uint32_t a2[4] = {__float_as_uint(qa2.x), __float_as_uint(qa2.y),
                              __float_as_uint(qa2.z), __float_as_uint(qa2.w)};
            uint32_t bb2[2] = {__float_as_uint(kb2.x), __float_as_uint(kb2.y)};
            mma_tf32(so, a2, bb2);
        }
        float sacc[4];
        #pragma unroll
        for (int q = 0; q < 4; q++) sacc[q] = se[q] + so[q];

        // ---- causal mask + row max ----
        const int row0 = m0 + r0, row1 = row0 + 8;
        const int cb = kv0 + wn * 8 + 2 * tig;
        if (cb     > row0) sacc[0] = -INFINITY;
        if (cb + 1 > row0) sacc[1] = -INFINITY;
        if (cb     > row1) sacc[2] = -INFINITY;
        if (cb + 1 > row1) sacc[3] = -INFINITY;
        float mx0 = fmaxf(sacc[0], sacc[1]);
        float mx1 = fmaxf(sacc[2], sacc[3]);
        mx0 = fmaxf(mx0, __shfl_xor_sync(0xffffffffu, mx0, 1));
        mx0 = fmaxf(mx0, __shfl_xor_sync(0xffffffffu, mx0, 2));
        mx1 = fmaxf(mx1, __shfl_xor_sync(0xffffffffu, mx1, 1));
        mx1 = fmaxf(mx1, __shfl_xor_sync(0xffffffffu, mx1, 2));
        if (tig == 0) {
            redmax[wn * 64 + r0]     = mx0;
            redmax[wn * 64 + r0 + 8] = mx1;
        }
        asm volatile("bar.sync %0, 128;" :: "r"(1 + wm) : "memory");
        float tm0 = fmaxf(fmaxf(redmax[r0],       redmax[64 + r0]),
                          fmaxf(redmax[128 + r0], redmax[192 + r0]));
        float tm1 = fmaxf(fmaxf(redmax[r0 + 8],       redmax[64 + r0 + 8]),
                          fmaxf(redmax[128 + r0 + 8], redmax[192 + r0 + 8]));
        float mnew0 = fmaxf(m_run0, tm0), mnew1 = fmaxf(m_run1, tm1);
        float alpha0 = __expf(m_run0 - mnew0), alpha1 = __expf(m_run1 - mnew1);
        m_run0 = mnew0; m_run1 = mnew1;

        // ---- exp, P write (tf32-rounded), partial sums ----
        const int cl = wn * 8 + 2 * tig;
        float e0 = __expf(sacc[0] - mnew0);
        float e1 = __expf(sacc[1] - mnew0);
        float e2 = __expf(sacc[2] - mnew1);
        float e3 = __expf(sacc[3] - mnew1);
        *(float2*)&Ps[r0 * PADP + cl] =
            make_float2(__uint_as_float(f2tf32(e0)), __uint_as_float(f2tf32(e1)));
        *(float2*)&Ps[(r0 + 8) * PADP + cl] =
            make_float2(__uint_as_float(f2tf32(e2)), __uint_as_float(f2tf32(e3)));
        float ps0 = e0 + e1, ps1 = e2 + e3;
        ps0 += __shfl_xor_sync(0xffffffffu, ps0, 1);
        ps0 += __shfl_xor_sync(0xffffffffu, ps0, 2);
        ps1 += __shfl_xor_sync(0xffffffffu, ps1, 1);
        ps1 += __shfl_xor_sync(0xffffffffu, ps1, 2);
        if (tig == 0) {
            redsum[wn * 64 + r0]     = ps0;
            redsum[wn * 64 + r0 + 8] = ps1;
        }
        asm volatile("bar.sync %0, 128;" :: "r"(1 + wm) : "memory");
        l_run0 = l_run0 * alpha0 + redsum[r0] + redsum[64 + r0]
               + redsum[128 + r0] + redsum[192 + r0];
        l_run1 = l_run1 * alpha1 + redsum[r0 + 8] + redsum[64 + r0 + 8]
               + redsum[128 + r0 + 8] + redsum[192 + r0 + 8];

        // ---- rescale O ----
        #pragma unroll
        for (int nt = 0; nt < 8; nt++) {
            o[nt][0] *= alpha0; o[nt][1] *= alpha0;
            o[nt][2] *= alpha1; o[nt][3] *= alpha1;
        }

        // ---- O += P V (warp owns 64 dims = wn slice) ----
        #pragma unroll
        for (int k8i = 0; k8i < 4; k8i++) {
            int k8 = k8i * 8;
            uint32_t a[4];
            a[0] = __float_as_uint(Ps[r0 * PADP + k8 + tig]);
            a[1] = __float_as_uint(Ps[(r0 + 8) * PADP + k8 + tig]);
            a[2] = __float_as_uint(Ps[r0 * PADP + k8 + tig + 4]);
            a[3] = __float_as_uint(Ps[(r0 + 8) * PADP + k8 + tig + 4]);
            #pragma unroll
            for (int ntp = 0; ntp < 4; ntp++) {
                float4 bv = Vp4[((k8i * 4 + wn) * 4 + ntp) * 32 + lane];
                uint32_t b0[2] = {__float_as_uint(bv.x), __float_as_uint(bv.y)};
                uint32_t b1[2] = {__float_as_uint(bv.z), __float_as_uint(bv.w)};
                mma_tf32(o[2 * ntp],     a, b0);
                mma_tf32(o[2 * ntp + 1], a, b1);
            }
        }
        __syncthreads();   // buffers + Ps consumed; safe to refill next iter
    }

    // ---- epilogue ----
    float inv0 = 1.f / l_run0, inv1 = 1.f / l_run1;
    float* ob = out + ((size_t)b * Tn + m0) * Hn;
    #pragma unroll
    for (int nt = 0; nt < 8; nt++) {
        int col = wn * 64 + nt * 8 + 2 * tig;
        *(float2*)&ob[(size_t)r0 * Hn + col] =
            make_float2(o[nt][0] * inv0, o[nt][1] * inv0);
        *(float2*)&ob[(size_t)(r0 + 8) * Hn + col] =
            make_float2(o[nt][2] * inv1, o[nt][3] * inv1);
    }
}

extern "C" void kernel_launch(void* const* d_in, const int* in_sizes, int n_in,
                              void* d_out, int out_size) {
    const float* x  = (const float*)d_in[0];
    const float* Wq = (const float*)d_in[1];
    const float* Wk = (const float*)d_in[2];
    const float* Wv = (const float*)d_in[3];
    float* out = (float*)d_out;

    pack_w_kernel<<<dim3(32, 3), 256>>>(Wq, Wk, Wv);

    cudaFuncSetAttribute(proj_wmma_kernel,
                         cudaFuncAttributeMaxDynamicSharedMemorySize, PROJ_SMEM);
    proj_wmma_kernel<<<dim3(Mn / 128, 2, 3), 256, PROJ_SMEM>>>(x);

    pack_q_kernel<<<dim3(Tn / 32, Bn), 256>>>();
    pack_k_kernel<<<dim3(Tn / 32, Bn), 256>>>();
    pack_v_kernel<<<dim3(Tn / 32, Bn), 256>>>();

    cudaFuncSetAttribute(attn_mma_kernel,
                         cudaFuncAttributeMaxDynamicSharedMemorySize, ATTN_SMEM);
    attn_mma_kernel<<<dim3(Tn / 64, Bn), 512, ATTN_SMEM>>>(out);
}

// round 12
// speedup vs baseline: 1.0266x; 1.0266x over previous
#include <cuda_runtime.h>
#include <math.h>
#include <cstdint>

#define Bn 8
#define Tn 2048
#define Cn 1024
#define Hn 256
#define Mn (Bn * Tn)   // 16384

// Scratch (allocation-free rule: __device__ globals)
__device__ float g_Q[Mn * Hn];       // [b][T][H]  (tf32-rounded)
__device__ float g_K[Mn * Hn];       // [b][T][H]  (tf32-rounded)
__device__ float g_V[Mn * Hn];       // [b][T][H]  (tf32-rounded)
__device__ float g_Qp[Mn * Hn];      // Q packed as mma A-fragments (scaled)
__device__ float g_Kp[Mn * Hn];      // K packed as S-GEMM B-fragments
__device__ float g_Vp[Mn * Hn];      // V packed as PV B-fragments
__device__ float g_Wp[3 * Hn * Cn];  // W packed as proj B-fragments (tf32 RNA)

// ---------------------------------------------------------------------------
// Helpers
// ---------------------------------------------------------------------------
__device__ __forceinline__ uint32_t smem_u32(const void* p) {
    uint32_t a;
    asm("{ .reg .u64 t; cvta.to.shared.u64 t, %1; cvt.u32.u64 %0, t; }"
        : "=r"(a) : "l"(p));
    return a;
}
__device__ __forceinline__ uint32_t f2tf32(float f) {
    uint32_t u;
    asm("cvt.rna.tf32.f32 %0, %1;" : "=r"(u) : "f"(f));
    return u;
}
__device__ __forceinline__ void cp_async16(uint32_t saddr, const void* g) {
    asm volatile("cp.async.cg.shared.global [%0], [%1], 16;"
                 :: "r"(saddr), "l"(g) : "memory");
}
__device__ __forceinline__ void cp_commit() {
    asm volatile("cp.async.commit_group;" ::: "memory");
}
__device__ __forceinline__ void mma_tf32(float* c, const uint32_t* a, const uint32_t* b) {
    asm volatile(
        "mma.sync.aligned.m16n8k8.row.col.f32.tf32.tf32.f32 "
        "{%0,%1,%2,%3}, {%4,%5,%6,%7}, {%8,%9}, {%0,%1,%2,%3};"
        : "+f"(c[0]), "+f"(c[1]), "+f"(c[2]), "+f"(c[3])
        : "r"(a[0]), "r"(a[1]), "r"(a[2]), "r"(a[3]), "r"(b[0]), "r"(b[1]));
}

// ---------------------------------------------------------------------------
// Pack W into proj B-fragment order, tf32-rounded (RNA). (unchanged R10)
// ---------------------------------------------------------------------------
__global__ __launch_bounds__(256)
void pack_w_kernel(const float* __restrict__ Wq,
                   const float* __restrict__ Wk,
                   const float* __restrict__ Wv) {
    __shared__ float vs[32][260];
    const int t     = blockIdx.x;
    const int which = blockIdx.y;
    const int tid   = threadIdx.x;
    const float* W = (which == 0) ? Wq : (which == 1 ? Wk : Wv);

    #pragma unroll
    for (int it = 0; it < 8; it++) {
        int f = tid + it * 256;
        int r = f >> 6, c4 = (f & 63) * 4;
        *(float4*)&vs[r][c4] = *(const float4*)&W[(size_t)(t * 32 + r) * Hn + c4];
    }
    __syncthreads();

    float* dstw = g_Wp + (size_t)which * 2 * 32 * 4096;
    #pragma unroll
    for (int it = 0; it < 8; it++) {
        int f = tid + it * 256;
        int n0b = f >> 10, rem = f & 1023;
        int k8 = rem >> 8, wn = (rem >> 7) & 1, ntp = (rem >> 5) & 3, lane = rem & 31;
        int g = lane >> 2, tt = lane & 3;
        int kc = k8 * 8 + tt;
        int n_a = n0b * 128 + wn * 64 + ntp * 16 + g, n_b = n_a + 8;
        float* dst = dstw + ((size_t)n0b * 32 + t) * 4096 + (size_t)rem * 4;
        *(float4*)dst = make_float4(
            __uint_as_float(f2tf32(vs[kc][n_a])),
            __uint_as_float(f2tf32(vs[kc + 4][n_a])),
            __uint_as_float(f2tf32(vs[kc][n_b])),
            __uint_as_float(f2tf32(vs[kc + 4][n_b])));
    }
}

// ---------------------------------------------------------------------------
// Projection via mma.sync tf32, B pre-packed. (unchanged R10)
// ---------------------------------------------------------------------------
#define AROW 36
#define ATILE_B (128 * AROW * 4)
#define BTILE_B 16384
#define OFF_PA0 0
#define OFF_PA1 ATILE_B
#define OFF_PB0 (2 * ATILE_B)
#define OFF_PB1 (2 * ATILE_B + BTILE_B)
#define PROJ_SMEM (2 * ATILE_B + 2 * BTILE_B)

__global__ __launch_bounds__(256, 2)
void proj_wmma_kernel(const float* __restrict__ x) {
    extern __shared__ char smem[];
    const uint32_t sb = smem_u32(smem);

    const int tid  = threadIdx.x;
    const int warp = tid >> 5, lane = tid & 31;
    const int group = lane >> 2, tig = lane & 3;
    const int wm = warp & 3, wn = warp >> 2;
    const int which = blockIdx.z;
    const int m0 = blockIdx.x * 128;
    const int n0b = blockIdx.y;

    const float* A = x + (size_t)m0 * Cn;
    const float* Bp = g_Wp + (((size_t)which * 2 + n0b) * 32) * 4096;
    float* outp = ((which == 0) ? g_Q : (which == 1 ? g_K : g_V))
                  + (size_t)m0 * Hn + n0b * 128;

    const int r0f = tid >> 3;
    const int ccf = (tid & 7) * 4;

    auto fill = [&](int t, int bsel) {
        const uint32_t aOff = sb + (bsel ? OFF_PA1 : OFF_PA0);
        const uint32_t bOff = sb + (bsel ? OFF_PB1 : OFF_PB0);
        #pragma unroll
        for (int it = 0; it < 4; it++) {
            int row = r0f + 32 * it;
            cp_async16(aOff + (uint32_t)(row * AROW + ccf) * 4,
                       A + (size_t)row * Cn + t * 32 + ccf);
        }
        const float* Bt = Bp + (size_t)t * 4096;
        #pragma unroll
        for (int it = 0; it < 4; it++) {
            int f = tid + it * 256;
            cp_async16(bOff + (uint32_t)f * 16, Bt + (size_t)f * 4);
        }
    };

    float acc[2][8][4];
    #pragma unroll
    for (int mt = 0; mt < 2; mt++)
        #pragma unroll
        for (int nt = 0; nt < 8; nt++)
            #pragma unroll
            for (int q = 0; q < 4; q++) acc[mt][nt][q] = 0.f;

    fill(0, 0);
    cp_commit();

    const int NT = Cn / 32;
    #pragma unroll 1
    for (int t = 0; t < NT; t++) {
        if (t + 1 < NT) {
            fill(t + 1, (t + 1) & 1);
            cp_commit();
            asm volatile("cp.async.wait_group 1;" ::: "memory");
        } else {
            asm volatile("cp.async.wait_group 0;" ::: "memory");
        }
        __syncthreads();

        const float* As = (const float*)(smem + ((t & 1) ? OFF_PA1 : OFF_PA0));
        const float4* Bs4 = (const float4*)(smem + ((t & 1) ? OFF_PB1 : OFF_PB0));

        #pragma unroll
        for (int k8 = 0; k8 < 4; k8++) {
            uint32_t a[2][4];
            #pragma unroll
            for (int mt = 0; mt < 2; mt++) {
                int m = wm * 32 + mt * 16 + group;
                a[mt][0] = f2tf32(As[m * AROW + k8 * 8 + tig]);
                a[mt][1] = f2tf32(As[(m + 8) * AROW + k8 * 8 + tig]);
                a[mt][2] = f2tf32(As[m * AROW + k8 * 8 + tig + 4]);
                a[mt][3] = f2tf32(As[(m + 8) * AROW + k8 * 8 + tig + 4]);
            }
            #pragma unroll
            for (int ntp = 0; ntp < 4; ntp++) {
                float4 bv = Bs4[((k8 * 2 + wn) * 4 + ntp) * 32 + lane];
                uint32_t b0[2] = {__float_as_uint(bv.x), __float_as_uint(bv.y)};
                uint32_t b1[2] = {__float_as_uint(bv.z), __float_as_uint(bv.w)};
                #pragma unroll
                for (int mt = 0; mt < 2; mt++) {
                    mma_tf32(acc[mt][2 * ntp],     a[mt], b0);
                    mma_tf32(acc[mt][2 * ntp + 1], a[mt], b1);
                }
            }
        }
        __syncthreads();
    }

    #pragma unroll
    for (int mt = 0; mt < 2; mt++) {
        int m = wm * 32 + mt * 16 + group;
        #pragma unroll
        for (int nt = 0; nt < 8; nt++) {
            int col = wn * 64 + nt * 8 + 2 * tig;
            *(float2*)&outp[(size_t)m * Hn + col] =
                make_float2(__uint_as_float(f2tf32(acc[mt][nt][0])),
                            __uint_as_float(f2tf32(acc[mt][nt][1])));
            *(float2*)&outp[(size_t)(m + 8) * Hn + col] =
                make_float2(__uint_as_float(f2tf32(acc[mt][nt][2])),
                            __uint_as_float(f2tf32(acc[mt][nt][3])));
        }
    }
}

// ---------------------------------------------------------------------------
// Pack Q into A-fragment order (scaled by 1/16), per 16-row block. (R10)
// ---------------------------------------------------------------------------
__global__ __launch_bounds__(256)
void pack_q_kernel() {
    __shared__ float vs[32][260];
    const int b   = blockIdx.y;
    const int t0  = blockIdx.x * 32;
    const int tid = threadIdx.x;
    const float* src = g_Q + ((size_t)b * Tn + t0) * Hn;
    float* dst = g_Qp + ((size_t)b * (Tn / 16) + blockIdx.x * 2) * 4096;
    const float scale = 0.0625f;

    #pragma unroll
    for (int it = 0; it < 8; it++) {
        int f = tid + it * 256;
        int r = f >> 6, c4 = (f & 63) * 4;
        float4 v = *(const float4*)&src[(size_t)r * Hn + c4];
        v.x *= scale; v.y *= scale; v.z *= scale; v.w *= scale;
        *(float4*)&vs[r][c4] = v;
    }
    __syncthreads();

    #pragma unroll
    for (int it = 0; it < 8; it++) {
        int f = tid + it * 256;
        int blk = f >> 10, rem = f & 1023;
        int k8 = rem >> 5, lane = rem & 31;
        int g = lane >> 2, t = lane & 3;
        int r0 = blk * 16 + g, r1 = r0 + 8;
        int c = k8 * 8 + t;
        *(float4*)&dst[(size_t)f * 4] =
            make_float4(vs[r0][c], vs[r1][c], vs[r0][c + 4], vs[r1][c + 4]);
    }
}

// ---------------------------------------------------------------------------
// Pack K into S-GEMM B-fragment order, per 32-key block (R10 format):
// [k8(32)][wh(2)][lane(32)][4] =
//   {K[n0][c], K[n0][c+4], K[n1][c], K[n1][c+4]}, n0=wh*16+g, n1=n0+8
// ---------------------------------------------------------------------------
__global__ __launch_bounds__(256)
void pack_k_kernel() {
    __shared__ float vs[32][260];
    const int b   = blockIdx.y;
    const int t0  = blockIdx.x * 32;
    const int tid = threadIdx.x;
    const float* src = g_K + ((size_t)b * Tn + t0) * Hn;
    float* dst = g_Kp + ((size_t)b * (Tn / 32) + blockIdx.x) * 8192;

    #pragma unroll
    for (int it = 0; it < 8; it++) {
        int f = tid + it * 256;
        int r = f >> 6, c4 = (f & 63) * 4;
        *(float4*)&vs[r][c4] = *(const float4*)&src[(size_t)r * Hn + c4];
    }
    __syncthreads();

    #pragma unroll
    for (int it = 0; it < 8; it++) {
        int f = tid + it * 256;
        int k8 = f >> 6, wh = (f >> 5) & 1, lane = f & 31;
        int g = lane >> 2, t = lane & 3;
        int n0 = wh * 16 + g, n1 = n0 + 8;
        int c = k8 * 8 + t;
        *(float4*)&dst[(size_t)f * 4] =
            make_float4(vs[n0][c], vs[n0][c + 4], vs[n1][c], vs[n1][c + 4]);
    }
}

// ---------------------------------------------------------------------------
// Pack V into PV B-fragment order, per 32-key block (R10 format):
// [k8i(4)][wn(2)][ntp(8)][lane(32)][4] =
//   {V[k0][d0], V[k1][d0], V[k0][d1], V[k1][d1]},
//   k0=k8i*8+tig, k1=k0+4, d0=wn*128+2*ntp*8+g, d1=d0+8
// ---------------------------------------------------------------------------
__global__ __launch_bounds__(256)
void pack_v_kernel() {
    __shared__ float vs[32][260];
    const int b   = blockIdx.y;
    const int t0  = blockIdx.x * 32;
    const int tid = threadIdx.x;
    const float* src = g_V + ((size_t)b * Tn + t0) * Hn;
    float* dst = g_Vp + ((size_t)b * (Tn / 32) + blockIdx.x) * 8192;

    #pragma unroll
    for (int it = 0; it < 8; it++) {
        int f = tid + it * 256;
        int r = f >> 6, c4 = (f & 63) * 4;
        *(float4*)&vs[r][c4] = *(const float4*)&src[(size_t)r * Hn + c4];
    }
    __syncthreads();

    #pragma unroll
    for (int it = 0; it < 8; it++) {
        int f = tid + it * 256;
        int k8i = f >> 9, wn = (f >> 8) & 1, ntp = (f >> 5) & 7, lane = f & 31;
        int group = lane >> 2, tig = lane & 3;
        int k0 = k8i * 8 + tig, k1 = k0 + 4;
        int d0 = wn * 128 + 2 * ntp * 8 + group, d1 = d0 + 8;
        *(float4*)&dst[(size_t)f * 4] =
            make_float4(vs[k0][d0], vs[k1][d0], vs[k0][d1], vs[k1][d1]);
    }
}

// ---------------------------------------------------------------------------
// Causal flash attention, mma.sync tf32 — BARRIER-FREE softmax.
// BM=64, BN=32, 8 warps: wm=warp>>1 (16-row group), wn=warp&1 (128-dim half).
// Each warp computes the FULL 16x32 S tile (redundant across the wn pair),
// so row max/sum are warp-local (quad shuffles only). P is converted from
// C-fragment to A-fragment layout entirely in registers (shuffle transpose):
//   P[r][col]: lane = (r%8)*4 + col>>1, reg sel = col&1 (+2 for r>=8)
//   a-frag needs cols t and t+4 -> srcA = quadbase + (t>>1), srcB = srcA+2.
// Only syncs per tile: 2 __syncthreads for cp.async K/V buffer rotation.
// ---------------------------------------------------------------------------
#define QP_BYTES 65536
#define KBUF 32768
#define OFF_QP 0
#define OFF_K0 QP_BYTES                     // 65536
#define OFF_V0 (OFF_K0 + 2 * KBUF)          // 131072
#define ATTN_SMEM (OFF_V0 + 2 * KBUF)       // 196608

__global__ __launch_bounds__(256, 1)
void attn_mma_kernel(float* __restrict__ out) {
    extern __shared__ char smem[];
    const uint32_t sb = smem_u32(smem);

    const int b   = blockIdx.y;
    const int m0  = ((int)gridDim.x - 1 - (int)blockIdx.x) * 64;
    const int tid = threadIdx.x;
    const int warp = tid >> 5, lane = tid & 31;
    const int group = lane >> 2, tig = lane & 3;
    const int wm = warp >> 1, wn = warp & 1;

    const float* Qpb = g_Qp + ((size_t)b * (Tn / 16) + m0 / 16) * 4096;
    const float* Kpb = g_Kp + (size_t)b * (Tn / 32) * 8192;
    const float* Vpb = g_Vp + (size_t)b * (Tn / 32) * 8192;

    auto fillK = [&](int t, int bs) {
        const uint32_t off = sb + OFF_K0 + bs * KBUF;
        const float* src = Kpb + (size_t)t * 8192;
        #pragma unroll
        for (int it = 0; it < 8; it++) {
            int f = tid + it * 256;
            cp_async16(off + (uint32_t)f * 16, src + (size_t)f * 4);
        }
    };
    auto fillV = [&](int t, int bs) {
        const uint32_t off = sb + OFF_V0 + bs * KBUF;
        const float* src = Vpb + (size_t)t * 8192;
        #pragma unroll
        for (int it = 0; it < 8; it++) {
            int f = tid + it * 256;
            cp_async16(off + (uint32_t)f * 16, src + (size_t)f * 4);
        }
    };

    // Stage Q (4096 float4) + first K/V
    #pragma unroll
    for (int it = 0; it < 16; it++) {
        int f = tid + it * 256;
        cp_async16(sb + OFF_QP + (uint32_t)f * 16, Qpb + (size_t)f * 4);
    }
    fillK(0, 0);
    fillV(0, 0);
    cp_commit();

    const int r0 = wm * 16 + group;          // owned rows r0, r0+8
    float m_run0 = -INFINITY, m_run1 = -INFINITY;
    float l_run0 = 0.f, l_run1 = 0.f;
    float o[16][4];
    #pragma unroll
    for (int nt = 0; nt < 16; nt++)
        #pragma unroll
        for (int q = 0; q < 4; q++) o[nt][q] = 0.f;

    const int srcA = (lane & 28) | (tig >> 1);
    const int srcB = srcA + 2;
    const int odd  = tig & 1;

    const int NT = m0 / 32 + 2;
    #pragma unroll 1
    for (int t = 0; t < NT; t++) {
        const int bs = t & 1;
        if (t + 1 < NT) {
            fillK(t + 1, bs ^ 1);
            fillV(t + 1, bs ^ 1);
            cp_commit();
            asm volatile("cp.async.wait_group 1;" ::: "memory");
        } else {
            asm volatile("cp.async.wait_group 0;" ::: "memory");
        }
        __syncthreads();

        const float4* Qw  = (const float4*)(smem + OFF_QP) + wm * 1024;
        const float4* Ks4 = (const float4*)(smem + OFF_K0 + bs * KBUF);
        const float4* Vp4 = (const float4*)(smem + OFF_V0 + bs * KBUF);
        const int kv0 = t * 32;

        // ---- S = Q K^T: FULL 16x32 per warp (4 n-tiles) ----
        float sacc[4][4];
        #pragma unroll
        for (int nt = 0; nt < 4; nt++)
            #pragma unroll
            for (int q = 0; q < 4; q++) sacc[nt][q] = 0.f;

        #pragma unroll 8
        for (int k8 = 0; k8 < 32; k8++) {
            float4 qa  = Qw[k8 * 32 + lane];
            float4 kb0 = Ks4[(k8 * 2 + 0) * 32 + lane];
            float4 kb1 = Ks4[(k8 * 2 + 1) * 32 + lane];
            uint32_t a[4] = {__float_as_uint(qa.x), __float_as_uint(qa.y),
                             __float_as_uint(qa.z), __float_as_uint(qa.w)};
            uint32_t b0[2] = {__float_as_uint(kb0.x), __float_as_uint(kb0.y)};
            uint32_t b1[2] = {__float_as_uint(kb0.z), __float_as_uint(kb0.w)};
            uint32_t b2[2] = {__float_as_uint(kb1.x), __float_as_uint(kb1.y)};
            uint32_t b3[2] = {__float_as_uint(kb1.z), __float_as_uint(kb1.w)};
            mma_tf32(sacc[0], a, b0);
            mma_tf32(sacc[1], a, b1);
            mma_tf32(sacc[2], a, b2);
            mma_tf32(sacc[3], a, b3);
        }

        // ---- causal mask + WARP-LOCAL row max ----
        const int row0 = m0 + r0, row1 = row0 + 8;
        float mx0 = -INFINITY, mx1 = -INFINITY;
        #pragma unroll
        for (int nt = 0; nt < 4; nt++) {
            int cb = kv0 + nt * 8 + 2 * tig;
            if (cb     > row0) sacc[nt][0] = -INFINITY;
            if (cb + 1 > row0) sacc[nt][1] = -INFINITY;
            if (cb     > row1) sacc[nt][2] = -INFINITY;
            if (cb + 1 > row1) sacc[nt][3] = -INFINITY;
            mx0 = fmaxf(mx0, fmaxf(sacc[nt][0], sacc[nt][1]));
            mx1 = fmaxf(mx1, fmaxf(sacc[nt][2], sacc[nt][3]));
        }
        mx0 = fmaxf(mx0, __shfl_xor_sync(0xffffffffu, mx0, 1));
        mx0 = fmaxf(mx0, __shfl_xor_sync(0xffffffffu, mx0, 2));
        mx1 = fmaxf(mx1, __shfl_xor_sync(0xffffffffu, mx1, 1));
        mx1 = fmaxf(mx1, __shfl_xor_sync(0xffffffffu, mx1, 2));
        float mnew0 = fmaxf(m_run0, mx0), mnew1 = fmaxf(m_run1, mx1);
        float alpha0 = __expf(m_run0 - mnew0), alpha1 = __expf(m_run1 - mnew1);
        m_run0 = mnew0; m_run1 = mnew1;

        // ---- exp (in place) + warp-local row sums ----
        float ps0 = 0.f, ps1 = 0.f;
        #pragma unroll
        for (int nt = 0; nt < 4; nt++) {
            sacc[nt][0] = __expf(sacc[nt][0] - mnew0);
            sacc[nt][1] = __expf(sacc[nt][1] - mnew0);
            sacc[nt][2] = __expf(sacc[nt][2] - mnew1);
            sacc[nt][3] = __expf(sacc[nt][3] - mnew1);
            ps0 += sacc[nt][0] + sacc[nt][1];
            ps1 += sacc[nt][2] + sacc[nt][3];
        }
        ps0 += __shfl_xor_sync(0xffffffffu, ps0, 1);
        ps0 += __shfl_xor_sync(0xffffffffu, ps0, 2);
        ps1 += __shfl_xor_sync(0xffffffffu, ps1, 1);
        ps1 += __shfl_xor_sync(0xffffffffu, ps1, 2);
        l_run0 = l_run0 * alpha0 + ps0;
        l_run1 = l_run1 * alpha1 + ps1;

        // ---- in-register C->A transpose of P (tf32-rounded) ----
        uint32_t afr[4][4];
        #pragma unroll
        for (int kc = 0; kc < 4; kc++) {
            float x0 = __shfl_sync(0xffffffffu, sacc[kc][0], srcA);
            float x1 = __shfl_sync(0xffffffffu, sacc[kc][1], srcA);
            float x2 = __shfl_sync(0xffffffffu, sacc[kc][2], srcA);
            float x3 = __shfl_sync(0xffffffffu, sacc[kc][3], srcA);
            float y0 = __shfl_sync(0xffffffffu, sacc[kc][0], srcB);
            float y1 = __shfl_sync(0xffffffffu, sacc[kc][1], srcB);
            float y2 = __shfl_sync(0xffffffffu, sacc[kc][2], srcB);
            float y3 = __shfl_sync(0xffffffffu, sacc[kc][3], srcB);
            afr[kc][0] = f2tf32(odd ? x1 : x0);
            afr[kc][1] = f2tf32(odd ? x3 : x2);
            afr[kc][2] = f2tf32(odd ? y1 : y0);
            afr[kc][3] = f2tf32(odd ? y3 : y2);
        }

        // ---- rescale O ----
        #pragma unroll
        for (int nt = 0; nt < 16; nt++) {
            o[nt][0] *= alpha0; o[nt][1] *= alpha0;
            o[nt][2] *= alpha1; o[nt][3] *= alpha1;
        }

        // ---- O += P V (V packed fragments; warp owns wn*128 dims) ----
        #pragma unroll
        for (int kc = 0; kc < 4; kc++) {
            #pragma unroll
            for (int ntp = 0; ntp < 8; ntp++) {
                float4 bv = Vp4[((kc * 2 + wn) * 8 + ntp) * 32 + lane];
                uint32_t b0[2] = {__float_as_uint(bv.x), __float_as_uint(bv.y)};
                uint32_t b1[2] = {__float_as_uint(bv.z), __float_as_uint(bv.w)};
                mma_tf32(o[2 * ntp],     afr[kc], b0);
                mma_tf32(o[2 * ntp + 1], afr[kc], b1);
            }
        }
        __syncthreads();   // K/V buffers consumed; safe to refill next iter
    }

    // ---- epilogue ----
    float inv0 = 1.f / l_run0, inv1 = 1.f / l_run1;
    float* ob = out + ((size_t)b * Tn + m0) * Hn;
    #pragma unroll
    for (int nt = 0; nt < 16; nt++) {
        int col = wn * 128 + nt * 8 + 2 * tig;
        *(float2*)&ob[(size_t)r0 * Hn + col] =
            make_float2(o[nt][0] * inv0, o[nt][1] * inv0);
        *(float2*)&ob[(size_t)(r0 + 8) * Hn + col] =
            make_float2(o[nt][2] * inv1, o[nt][3] * inv1);
    }
}

extern "C" void kernel_launch(void* const* d_in, const int* in_sizes, int n_in,
                              void* d_out, int out_size) {
    const float* x  = (const float*)d_in[0];
    const float* Wq = (const float*)d_in[1];
    const float* Wk = (const float*)d_in[2];
    const float* Wv = (const float*)d_in[3];
    float* out = (float*)d_out;

    pack_w_kernel<<<dim3(32, 3), 256>>>(Wq, Wk, Wv);

    cudaFuncSetAttribute(proj_wmma_kernel,
                         cudaFuncAttributeMaxDynamicSharedMemorySize, PROJ_SMEM);
    proj_wmma_kernel<<<dim3(Mn / 128, 2, 3), 256, PROJ_SMEM>>>(x);

    pack_q_kernel<<<dim3(Tn / 32, Bn), 256>>>();
    pack_k_kernel<<<dim3(Tn / 32, Bn), 256>>>();
    pack_v_kernel<<<dim3(Tn / 32, Bn), 256>>>();

    cudaFuncSetAttribute(attn_mma_kernel,
                         cudaFuncAttributeMaxDynamicSharedMemorySize, ATTN_SMEM);
    attn_mma_kernel<<<dim3(Tn / 64, Bn), 256, ATTN_SMEM>>>(out);
}

// round 13
// speedup vs baseline: 1.1768x; 1.1463x over previous
#include <cuda_runtime.h>
#include <math.h>
#include <cstdint>

#define Bn 8
#define Tn 2048
#define Cn 1024
#define Hn 256
#define Mn (Bn * Tn)   // 16384

// Scratch (allocation-free rule: __device__ globals)
__device__ float g_V[Mn * Hn];       // [b][T][H]  (tf32-rounded)
__device__ float g_Qp[Mn * Hn];      // Q packed as mma A-fragments (scaled)
__device__ float g_Kp[Mn * Hn];      // K packed as S-GEMM B-fragments
__device__ float g_Vp[Mn * Hn];      // V packed as PV B-fragments
__device__ float g_Wp[3 * Hn * Cn];  // W packed as proj B-fragments (tf32 RNA)

// ---------------------------------------------------------------------------
// Helpers
// ---------------------------------------------------------------------------
__device__ __forceinline__ uint32_t smem_u32(const void* p) {
    uint32_t a;
    asm("{ .reg .u64 t; cvta.to.shared.u64 t, %1; cvt.u32.u64 %0, t; }"
        : "=r"(a) : "l"(p));
    return a;
}
__device__ __forceinline__ uint32_t f2tf32(float f) {
    uint32_t u;
    asm("cvt.rna.tf32.f32 %0, %1;" : "=r"(u) : "f"(f));
    return u;
}
__device__ __forceinline__ void cp_async16(uint32_t saddr, const void* g) {
    asm volatile("cp.async.cg.shared.global [%0], [%1], 16;"
                 :: "r"(saddr), "l"(g) : "memory");
}
__device__ __forceinline__ void cp_commit() {
    asm volatile("cp.async.commit_group;" ::: "memory");
}
__device__ __forceinline__ void mma_tf32(float* c, const uint32_t* a, const uint32_t* b) {
    asm volatile(
        "mma.sync.aligned.m16n8k8.row.col.f32.tf32.tf32.f32 "
        "{%0,%1,%2,%3}, {%4,%5,%6,%7}, {%8,%9}, {%0,%1,%2,%3};"
        : "+f"(c[0]), "+f"(c[1]), "+f"(c[2]), "+f"(c[3])
        : "r"(a[0]), "r"(a[1]), "r"(a[2]), "r"(a[3]), "r"(b[0]), "r"(b[1]));
}

// ---------------------------------------------------------------------------
// Pack W into proj B-fragment order, tf32-rounded (RNA). (unchanged R10)
// ---------------------------------------------------------------------------
__global__ __launch_bounds__(256)
void pack_w_kernel(const float* __restrict__ Wq,
                   const float* __restrict__ Wk,
                   const float* __restrict__ Wv) {
    __shared__ float vs[32][260];
    const int t     = blockIdx.x;
    const int which = blockIdx.y;
    const int tid   = threadIdx.x;
    const float* W = (which == 0) ? Wq : (which == 1 ? Wk : Wv);

    #pragma unroll
    for (int it = 0; it < 8; it++) {
        int f = tid + it * 256;
        int r = f >> 6, c4 = (f & 63) * 4;
        *(float4*)&vs[r][c4] = *(const float4*)&W[(size_t)(t * 32 + r) * Hn + c4];
    }
    __syncthreads();

    float* dstw = g_Wp + (size_t)which * 2 * 32 * 4096;
    #pragma unroll
    for (int it = 0; it < 8; it++) {
        int f = tid + it * 256;
        int n0b = f >> 10, rem = f & 1023;
        int k8 = rem >> 8, wn = (rem >> 7) & 1, ntp = (rem >> 5) & 3, lane = rem & 31;
        int g = lane >> 2, tt = lane & 3;
        int kc = k8 * 8 + tt;
        int n_a = n0b * 128 + wn * 64 + ntp * 16 + g, n_b = n_a + 8;
        float* dst = dstw + ((size_t)n0b * 32 + t) * 4096 + (size_t)rem * 4;
        *(float4*)dst = make_float4(
            __uint_as_float(f2tf32(vs[kc][n_a])),
            __uint_as_float(f2tf32(vs[kc + 4][n_a])),
            __uint_as_float(f2tf32(vs[kc][n_b])),
            __uint_as_float(f2tf32(vs[kc + 4][n_b])));
    }
}

// ---------------------------------------------------------------------------
// Projection via mma.sync tf32, B pre-packed.
// Epilogue writes Q/K DIRECTLY in packed fragment layouts (in-register
// C->fragment shuffle, validated in R12); V written natural for pack_v.
// ---------------------------------------------------------------------------
#define AROW 36
#define ATILE_B (128 * AROW * 4)
#define BTILE_B 16384
#define OFF_PA0 0
#define OFF_PA1 ATILE_B
#define OFF_PB0 (2 * ATILE_B)
#define OFF_PB1 (2 * ATILE_B + BTILE_B)
#define PROJ_SMEM (2 * ATILE_B + 2 * BTILE_B)

__global__ __launch_bounds__(256, 2)
void proj_wmma_kernel(const float* __restrict__ x) {
    extern __shared__ char smem[];
    const uint32_t sb = smem_u32(smem);

    const int tid  = threadIdx.x;
    const int warp = tid >> 5, lane = tid & 31;
    const int group = lane >> 2, tig = lane & 3;
    const int wm = warp & 3, wn = warp >> 2;
    const int which = blockIdx.z;
    const int m0 = blockIdx.x * 128;
    const int n0b = blockIdx.y;

    const float* A = x + (size_t)m0 * Cn;
    const float* Bp = g_Wp + (((size_t)which * 2 + n0b) * 32) * 4096;

    const int r0f = tid >> 3;
    const int ccf = (tid & 7) * 4;

    auto fill = [&](int t, int bsel) {
        const uint32_t aOff = sb + (bsel ? OFF_PA1 : OFF_PA0);
        const uint32_t bOff = sb + (bsel ? OFF_PB1 : OFF_PB0);
        #pragma unroll
        for (int it = 0; it < 4; it++) {
            int row = r0f + 32 * it;
            cp_async16(aOff + (uint32_t)(row * AROW + ccf) * 4,
                       A + (size_t)row * Cn + t * 32 + ccf);
        }
        const float* Bt = Bp + (size_t)t * 4096;
        #pragma unroll
        for (int it = 0; it < 4; it++) {
            int f = tid + it * 256;
            cp_async16(bOff + (uint32_t)f * 16, Bt + (size_t)f * 4);
        }
    };

    float acc[2][8][4];
    #pragma unroll
    for (int mt = 0; mt < 2; mt++)
        #pragma unroll
        for (int nt = 0; nt < 8; nt++)
            #pragma unroll
            for (int q = 0; q < 4; q++) acc[mt][nt][q] = 0.f;

    fill(0, 0);
    cp_commit();

    const int NT = Cn / 32;
    #pragma unroll 1
    for (int t = 0; t < NT; t++) {
        if (t + 1 < NT) {
            fill(t + 1, (t + 1) & 1);
            cp_commit();
            asm volatile("cp.async.wait_group 1;" ::: "memory");
        } else {
            asm volatile("cp.async.wait_group 0;" ::: "memory");
        }
        __syncthreads();

        const float* As = (const float*)(smem + ((t & 1) ? OFF_PA1 : OFF_PA0));
        const float4* Bs4 = (const float4*)(smem + ((t & 1) ? OFF_PB1 : OFF_PB0));

        #pragma unroll
        for (int k8 = 0; k8 < 4; k8++) {
            uint32_t a[2][4];
            #pragma unroll
            for (int mt = 0; mt < 2; mt++) {
                int m = wm * 32 + mt * 16 + group;
                a[mt][0] = f2tf32(As[m * AROW + k8 * 8 + tig]);
                a[mt][1] = f2tf32(As[(m + 8) * AROW + k8 * 8 + tig]);
                a[mt][2] = f2tf32(As[m * AROW + k8 * 8 + tig + 4]);
                a[mt][3] = f2tf32(As[(m + 8) * AROW + k8 * 8 + tig + 4]);
            }
            #pragma unroll
            for (int ntp = 0; ntp < 4; ntp++) {
                float4 bv = Bs4[((k8 * 2 + wn) * 4 + ntp) * 32 + lane];
                uint32_t b0[2] = {__float_as_uint(bv.x), __float_as_uint(bv.y)};
                uint32_t b1[2] = {__float_as_uint(bv.z), __float_as_uint(bv.w)};
                #pragma unroll
                for (int mt = 0; mt < 2; mt++) {
                    mma_tf32(acc[mt][2 * ntp],     a[mt], b0);
                    mma_tf32(acc[mt][2 * ntp + 1], a[mt], b1);
                }
            }
        }
        __syncthreads();
    }

    // ---- epilogue ----
    if (which == 2) {
        // V: natural layout (tf32-rounded) for pack_v
        float* outp = g_V + (size_t)m0 * Hn + n0b * 128;
        #pragma unroll
        for (int mt = 0; mt < 2; mt++) {
            int m = wm * 32 + mt * 16 + group;
            #pragma unroll
            for (int nt = 0; nt < 8; nt++) {
                int col = wn * 64 + nt * 8 + 2 * tig;
                *(float2*)&outp[(size_t)m * Hn + col] =
                    make_float2(__uint_as_float(f2tf32(acc[mt][nt][0])),
                                __uint_as_float(f2tf32(acc[mt][nt][1])));
                *(float2*)&outp[(size_t)(m + 8) * Hn + col] =
                    make_float2(__uint_as_float(f2tf32(acc[mt][nt][2])),
                                __uint_as_float(f2tf32(acc[mt][nt][3])));
            }
        }
    } else {
        // Q/K: in-register C->fragment shuffle, direct packed store.
        const int srcA = (lane & 28) | (tig >> 1);
        const int srcB = srcA + 2;
        const int odd  = tig & 1;
        #pragma unroll
        for (int mt = 0; mt < 2; mt++) {
            const int blk16 = (m0 >> 4) + wm * 2 + mt;   // global 16-row block
            #pragma unroll
            for (int nt = 0; nt < 8; nt++) {
                const int k8 = n0b * 16 + wn * 8 + nt;   // global 8-dim block
                float* c = acc[mt][nt];
                float x0 = __shfl_sync(0xffffffffu, c[0], srcA);
                float x1 = __shfl_sync(0xffffffffu, c[1], srcA);
                float x2 = __shfl_sync(0xffffffffu, c[2], srcA);
                float x3 = __shfl_sync(0xffffffffu, c[3], srcA);
                float y0 = __shfl_sync(0xffffffffu, c[0], srcB);
                float y1 = __shfl_sync(0xffffffffu, c[1], srcB);
                float y2 = __shfl_sync(0xffffffffu, c[2], srcB);
                float y3 = __shfl_sync(0xffffffffu, c[3], srcB);
                float a0 = odd ? x1 : x0;   // row g,   col t
                float a1 = odd ? x3 : x2;   // row g+8, col t
                float a2 = odd ? y1 : y0;   // row g,   col t+4
                float a3 = odd ? y3 : y2;   // row g+8, col t+4
                if (which == 0) {
                    const float s = 0.0625f;   // 1/sqrt(256), exact in tf32
                    uint4 v = make_uint4(f2tf32(a0 * s), f2tf32(a1 * s),
                                         f2tf32(a2 * s), f2tf32(a3 * s));
                    *(uint4*)(g_Qp + (size_t)blk16 * 4096
                              + (size_t)(k8 * 32 + lane) * 4) = v;
                } else {
                    // K B-frag order: {row g c, row g c+4, row g+8 c, row g+8 c+4}
                    uint4 v = make_uint4(f2tf32(a0), f2tf32(a2),
                                         f2tf32(a1), f2tf32(a3));
                    *(uint4*)(g_Kp + (size_t)(blk16 >> 1) * 8192
                              + (size_t)((k8 * 2 + (blk16 & 1)) * 32 + lane) * 4) = v;
                }
            }
        }
    }
}

// ---------------------------------------------------------------------------
// Pack V into PV B-fragment order, per 32-key block (R10 format).
// ---------------------------------------------------------------------------
__global__ __launch_bounds__(256)
void pack_v_kernel() {
    __shared__ float vs[32][260];
    const int b   = blockIdx.y;
    const int t0  = blockIdx.x * 32;
    const int tid = threadIdx.x;
    const float* src = g_V + ((size_t)b * Tn + t0) * Hn;
    float* dst = g_Vp + ((size_t)b * (Tn / 32) + blockIdx.x) * 8192;

    #pragma unroll
    for (int it = 0; it < 8; it++) {
        int f = tid + it * 256;
        int r = f >> 6, c4 = (f & 63) * 4;
        *(float4*)&vs[r][c4] = *(const float4*)&src[(size_t)r * Hn + c4];
    }
    __syncthreads();

    #pragma unroll
    for (int it = 0; it < 8; it++) {
        int f = tid + it * 256;
        int k8i = f >> 9, wn = (f >> 8) & 1, ntp = (f >> 5) & 7, lane = f & 31;
        int group = lane >> 2, tig = lane & 3;
        int k0 = k8i * 8 + tig, k1 = k0 + 4;
        int d0 = wn * 128 + 2 * ntp * 8 + group, d1 = d0 + 8;
        *(float4*)&dst[(size_t)f * 4] =
            make_float4(vs[k0][d0], vs[k1][d0], vs[k0][d1], vs[k1][d1]);
    }
}

// ---------------------------------------------------------------------------
// Causal flash attention, mma.sync tf32 (R10 structure + split S chains).
// BM=64, BN=32, 8 warps. wm=warp>>1, wn=warp&1 (SMSP-decoupled bar groups).
// ---------------------------------------------------------------------------
#define QP_BYTES 65536
#define KBUF 32768
#define OFF_QP 0
#define OFF_K0 QP_BYTES
#define OFF_V0 (OFF_K0 + 2 * KBUF)
#define OFF_PS (OFF_V0 + 2 * KBUF)
#define PADP 36
#define OFF_RED (OFF_PS + 64 * PADP * 4)
#define ATTN_SMEM (OFF_RED + 1024)

__global__ __launch_bounds__(256, 1)
void attn_mma_kernel(float* __restrict__ out) {
    extern __shared__ char smem[];
    const uint32_t sb = smem_u32(smem);
    float* Ps = (float*)(smem + OFF_PS);
    float* redmax = (float*)(smem + OFF_RED);
    float* redsum = redmax + 128;

    const int b   = blockIdx.y;
    const int m0  = ((int)gridDim.x - 1 - (int)blockIdx.x) * 64;
    const int tid = threadIdx.x;
    const int warp = tid >> 5, lane = tid & 31;
    const int group = lane >> 2, tig = lane & 3;
    const int wm = warp >> 1, wn = warp & 1;

    const float* Qpb = g_Qp + ((size_t)b * (Tn / 16) + m0 / 16) * 4096;
    const float* Kpb = g_Kp + (size_t)b * (Tn / 32) * 8192;
    const float* Vpb = g_Vp + (size_t)b * (Tn / 32) * 8192;

    auto fillK = [&](int t, int bs) {
        const uint32_t off = sb + OFF_K0 + bs * KBUF;
        const float* src = Kpb + (size_t)t * 8192;
        #pragma unroll
        for (int it = 0; it < 8; it++) {
            int f = tid + it * 256;
            cp_async16(off + (uint32_t)f * 16, src + (size_t)f * 4);
        }
    };
    auto fillV = [&](int t, int bs) {
        const uint32_t off = sb + OFF_V0 + bs * KBUF;
        const float* src = Vpb + (size_t)t * 8192;
        #pragma unroll
        for (int it = 0; it < 8; it++) {
            int f = tid + it * 256;
            cp_async16(off + (uint32_t)f * 16, src + (size_t)f * 4);
        }
    };

    #pragma unroll
    for (int it = 0; it < 16; it++) {
        int f = tid + it * 256;
        cp_async16(sb + OFF_QP + (uint32_t)f * 16, Qpb + (size_t)f * 4);
    }
    fillK(0, 0);
    fillV(0, 0);
    cp_commit();

    const int r0 = wm * 16 + group;
    float m_run0 = -INFINITY, m_run1 = -INFINITY;
    float l_run0 = 0.f, l_run1 = 0.f;
    float o[16][4];
    #pragma unroll
    for (int nt = 0; nt < 16; nt++)
        #pragma unroll
        for (int q = 0; q < 4; q++) o[nt][q] = 0.f;

    const int NT = m0 / 32 + 2;
    #pragma unroll 1
    for (int t = 0; t < NT; t++) {
        const int bs = t & 1;
        if (t + 1 < NT) {
            fillK(t + 1, bs ^ 1);
            fillV(t + 1, bs ^ 1);
            cp_commit();
            asm volatile("cp.async.wait_group 1;" ::: "memory");
        } else {
            asm volatile("cp.async.wait_group 0;" ::: "memory");
        }
        __syncthreads();

        const float4* Qw  = (const float4*)(smem + OFF_QP) + wm * 1024;
        const float4* Ks4 = (const float4*)(smem + OFF_K0 + bs * KBUF);
        const float4* Vp4 = (const float4*)(smem + OFF_V0 + bs * KBUF);
        const int kv0 = t * 32;

        // ---- S = Q K^T, even/odd-k8 split accumulator chains ----
        float se[2][4], so[2][4];
        #pragma unroll
        for (int nt = 0; nt < 2; nt++)
            #pragma unroll
            for (int q = 0; q < 4; q++) { se[nt][q] = 0.f; so[nt][q] = 0.f; }

        #pragma unroll 4
        for (int k8 = 0; k8 < 32; k8 += 2) {
            float4 qa = Qw[k8 * 32 + lane];
            float4 kb = Ks4[(k8 * 2 + wn) * 32 + lane];
            uint32_t a[4] = {__float_as_uint(qa.x), __float_as_uint(qa.y),
                             __float_as_uint(qa.z), __float_as_uint(qa.w)};
            uint32_t b0[2] = {__float_as_uint(kb.x), __float_as_uint(kb.y)};
            uint32_t b1[2] = {__float_as_uint(kb.z), __float_as_uint(kb.w)};
            mma_tf32(se[0], a, b0);
            mma_tf32(se[1], a, b1);

            float4 qa2 = Qw[(k8 + 1) * 32 + lane];
            float4 kb2 = Ks4[((k8 + 1) * 2 + wn) * 32 + lane];
            uint32_t a2[4] = {__float_as_uint(qa2.x), __float_as_uint(qa2.y),
                              __float_as_uint(qa2.z), __float_as_uint(qa2.w)};
            uint32_t b2[2] = {__float_as_uint(kb2.x), __float_as_uint(kb2.y)};
            uint32_t b3[2] = {__float_as_uint(kb2.z), __float_as_uint(kb2.w)};
            mma_tf32(so[0], a2, b2);
            mma_tf32(so[1], a2, b3);
        }
        float sacc[2][4];
        #pragma unroll
        for (int nt = 0; nt < 2; nt++)
            #pragma unroll
            for (int q = 0; q < 4; q++) sacc[nt][q] = se[nt][q] + so[nt][q];

        // ---- causal mask + row max ----
        const int row0 = m0 + r0, row1 = row0 + 8;
        float mx0 = -INFINITY, mx1 = -INFINITY;
        #pragma unroll
        for (int nt = 0; nt < 2; nt++) {
            int cb = kv0 + wn * 16 + nt * 8 + 2 * tig;
            if (cb     > row0) sacc[nt][0] = -INFINITY;
            if (cb + 1 > row0) sacc[nt][1] = -INFINITY;
            if (cb     > row1) sacc[nt][2] = -INFINITY;
            if (cb + 1 > row1) sacc[nt][3] = -INFINITY;
            mx0 = fmaxf(mx0, fmaxf(sacc[nt][0], sacc[nt][1]));
            mx1 = fmaxf(mx1, fmaxf(sacc[nt][2], sacc[nt][3]));
        }
        mx0 = fmaxf(mx0, __shfl_xor_sync(0xffffffffu, mx0, 1));
        mx0 = fmaxf(mx0, __shfl_xor_sync(0xffffffffu, mx0, 2));
        mx1 = fmaxf(mx1, __shfl_xor_sync(0xffffffffu, mx1, 1));
        mx1 = fmaxf(mx1, __shfl_xor_sync(0xffffffffu, mx1, 2));
        if (tig == 0) {
            redmax[wn * 64 + r0]     = mx0;
            redmax[wn * 64 + r0 + 8] = mx1;
        }
        asm volatile("bar.sync %0, 64;" :: "r"(1 + wm) : "memory");
        float mnew0 = fmaxf(m_run0, fmaxf(redmax[r0],     redmax[64 + r0]));
        float mnew1 = fmaxf(m_run1, fmaxf(redmax[r0 + 8], redmax[64 + r0 + 8]));
        float alpha0 = __expf(m_run0 - mnew0), alpha1 = __expf(m_run1 - mnew1);
        m_run0 = mnew0; m_run1 = mnew1;

        // ---- exp, P write (tf32-rounded), partial sums ----
        float ps0 = 0.f, ps1 = 0.f;
        #pragma unroll
        for (int nt = 0; nt < 2; nt++) {
            int cl = wn * 16 + nt * 8 + 2 * tig;
            float e0 = __expf(sacc[nt][0] - mnew0);
            float e1 = __expf(sacc[nt][1] - mnew0);
            float e2 = __expf(sacc[nt][2] - mnew1);
            float e3 = __expf(sacc[nt][3] - mnew1);
            ps0 += e0 + e1; ps1 += e2 + e3;
            *(float2*)&Ps[r0 * PADP + cl] =
                make_float2(__uint_as_float(f2tf32(e0)), __uint_as_float(f2tf32(e1)));
            *(float2*)&Ps[(r0 + 8) * PADP + cl] =
                make_float2(__uint_as_float(f2tf32(e2)), __uint_as_float(f2tf32(e3)));
        }
        ps0 += __shfl_xor_sync(0xffffffffu, ps0, 1);
        ps0 += __shfl_xor_sync(0xffffffffu, ps0, 2);
        ps1 += __shfl_xor_sync(0xffffffffu, ps1, 1);
        ps1 += __shfl_xor_sync(0xffffffffu, ps1, 2);
        if (tig == 0) {
            redsum[wn * 64 + r0]     = ps0;
            redsum[wn * 64 + r0 + 8] = ps1;
        }
        asm volatile("bar.sync %0, 64;" :: "r"(1 + wm) : "memory");
        l_run0 = l_run0 * alpha0 + redsum[r0]     + redsum[64 + r0];
        l_run1 = l_run1 * alpha1 + redsum[r0 + 8] + redsum[64 + r0 + 8];

        // ---- rescale O ----
        #pragma unroll
        for (int nt = 0; nt < 16; nt++) {
            o[nt][0] *= alpha0; o[nt][1] *= alpha0;
            o[nt][2] *= alpha1; o[nt][3] *= alpha1;
        }

        // ---- O += P V (V packed fragments: LDS.128) ----
        #pragma unroll
        for (int k8i = 0; k8i < 4; k8i++) {
            int k8 = k8i * 8;
            uint32_t a[4];
            a[0] = __float_as_uint(Ps[r0 * PADP + k8 + tig]);
            a[1] = __float_as_uint(Ps[(r0 + 8) * PADP + k8 + tig]);
            a[2] = __float_as_uint(Ps[r0 * PADP + k8 + tig + 4]);
            a[3] = __float_as_uint(Ps[(r0 + 8) * PADP + k8 + tig + 4]);
            #pragma unroll
            for (int ntp = 0; ntp < 8; ntp++) {
                float4 bv = Vp4[((k8i * 2 + wn) * 8 + ntp) * 32 + lane];
                uint32_t b0[2] = {__float_as_uint(bv.x), __float_as_uint(bv.y)};
                uint32_t b1[2] = {__float_as_uint(bv.z), __float_as_uint(bv.w)};
                mma_tf32(o[2 * ntp],     a, b0);
                mma_tf32(o[2 * ntp + 1], a, b1);
            }
        }
        __syncthreads();
    }

    // ---- epilogue ----
    float inv0 = 1.f / l_run0, inv1 = 1.f / l_run1;
    float* ob = out + ((size_t)b * Tn + m0) * Hn;
    #pragma unroll
    for (int nt = 0; nt < 16; nt++) {
        int col = wn * 128 + nt * 8 + 2 * tig;
        *(float2*)&ob[(size_t)r0 * Hn + col] =
            make_float2(o[nt][0] * inv0, o[nt][1] * inv0);
        *(float2*)&ob[(size_t)(r0 + 8) * Hn + col] =
            make_float2(o[nt][2] * inv1, o[nt][3] * inv1);
    }
}

extern "C" void kernel_launch(void* const* d_in, const int* in_sizes, int n_in,
                              void* d_out, int out_size) {
    const float* x  = (const float*)d_in[0];
    const float* Wq = (const float*)d_in[1];
    const float* Wk = (const float*)d_in[2];
    const float* Wv = (const float*)d_in[3];
    float* out = (float*)d_out;

    pack_w_kernel<<<dim3(32, 3), 256>>>(Wq, Wk, Wv);

    cudaFuncSetAttribute(proj_wmma_kernel,
                         cudaFuncAttributeMaxDynamicSharedMemorySize, PROJ_SMEM);
    proj_wmma_kernel<<<dim3(Mn / 128, 2, 3), 256, PROJ_SMEM>>>(x);

    pack_v_kernel<<<dim3(Tn / 32, Bn), 256>>>();

    cudaFuncSetAttribute(attn_mma_kernel,
                         cudaFuncAttributeMaxDynamicSharedMemorySize, ATTN_SMEM);
    attn_mma_kernel<<<dim3(Tn / 64, Bn), 256, ATTN_SMEM>>>(out);
}